// round 11
// baseline (speedup 1.0000x reference)
#include <cuda_runtime.h>
#include <math.h>

#define NB   32
#define NL   2048
#define ND   512
#define NDFF 256
#define NBLK 6
#define FEPS 1e-6f
#define LCHUNK 64
#define NCHUNK (NL / LCHUNK)   // 32

// ---------------- device scratch (no allocations allowed) ----------------
__device__ float g_q[NB * ND];              // evolving query
__device__ float g_scores[NB * NL];         // raw scores
__device__ float g_s[NB * NL];              // softmax probs (contiguous)
__device__ float g_Apart[NB * NCHUNK * ND]; // partial attention outputs
__device__ float g_sink;                    // DCE sink for warm loads

// ---------------- helpers ----------------
__device__ __forceinline__ float block_sum_512(float v, float* red) {
    #pragma unroll
    for (int o = 16; o; o >>= 1) v += __shfl_xor_sync(0xffffffffu, v, o);
    int w = threadIdx.x >> 5;
    if ((threadIdx.x & 31) == 0) red[w] = v;
    __syncthreads();
    if (threadIdx.x < 16) {
        float t = red[threadIdx.x];
        #pragma unroll
        for (int o = 8; o; o >>= 1) t += __shfl_xor_sync(0xffffu, t, o);
        if (threadIdx.x == 0) red[0] = t;
    }
    __syncthreads();
    float r = red[0];
    __syncthreads();
    return r;
}

__device__ __forceinline__ float dot4(float4 a, float4 b, float acc) {
    acc = fmaf(a.x, b.x, acc);
    acc = fmaf(a.y, b.y, acc);
    acc = fmaf(a.z, b.z, acc);
    acc = fmaf(a.w, b.w, acc);
    return acc;
}

// ---------------- kernels ----------------
__global__ void initq_kernel(const float* __restrict__ q) {
    int i = blockIdx.x * blockDim.x + threadIdx.x;
    if (i < NB * ND) g_q[i] = q[i];
}

// scores: TWO rows per warp; 8 x 16B loads in flight per lane (R9-measured best)
__global__ void scores_kernel(const float* __restrict__ k) {
    int warp = (blockIdx.x * blockDim.x + threadIdx.x) >> 5;  // 0..NB*NL/2-1
    int lane = threadIdx.x & 31;
    if (warp >= NB * NL / 2) return;
    int r0 = warp * 2;            // rows r0, r0+1 (same batch: 2048 rows per b)
    int b = r0 >> 11;
    const float4* kA = reinterpret_cast<const float4*>(k + (size_t)r0 * ND) + lane;
    const float4* kB = reinterpret_cast<const float4*>(k + (size_t)(r0 + 1) * ND) + lane;
    const float4* q4 = reinterpret_cast<const float4*>(g_q + b * ND) + lane;

    float4 a0 = __ldcs(kA + 0);
    float4 a1 = __ldcs(kA + 32);
    float4 a2 = __ldcs(kA + 64);
    float4 a3 = __ldcs(kA + 96);
    float4 b0 = __ldcs(kB + 0);
    float4 b1 = __ldcs(kB + 32);
    float4 b2 = __ldcs(kB + 64);
    float4 b3 = __ldcs(kB + 96);
    float4 q0 = q4[0], q1 = q4[32], q2 = q4[64], q3 = q4[96];

    float accA = 0.f, accB = 0.f;
    accA = dot4(a0, q0, accA); accB = dot4(b0, q0, accB);
    accA = dot4(a1, q1, accA); accB = dot4(b1, q1, accB);
    accA = dot4(a2, q2, accA); accB = dot4(b2, q2, accB);
    accA = dot4(a3, q3, accA); accB = dot4(b3, q3, accB);

    #pragma unroll
    for (int o = 16; o; o >>= 1) {
        accA += __shfl_xor_sync(0xffffffffu, accA, o);
        accB += __shfl_xor_sync(0xffffffffu, accB, o);
    }
    if (lane == 0) {
        const float s = 0.04419417382415922f;   // 1/sqrt(512)
        g_scores[r0]     = accA * s;
        g_scores[r0 + 1] = accB * s;
    }
}

// softmax over L per batch; writes contiguous g_s and strided weights[:, :, blk]
__global__ void softmax_kernel(float* __restrict__ wout, int blk) {
    int b = blockIdx.x;
    int t = threadIdx.x;            // 512 threads
    __shared__ float red[16];
    const float* sc = g_scores + b * NL;

    float e[NL / 512];
    float m = -INFINITY;
    #pragma unroll
    for (int i = 0; i < NL / 512; i++) {
        e[i] = sc[t + i * 512];
        m = fmaxf(m, e[i]);
    }
    #pragma unroll
    for (int o = 16; o; o >>= 1) m = fmaxf(m, __shfl_xor_sync(0xffffffffu, m, o));
    int w = t >> 5;
    if ((t & 31) == 0) red[w] = m;
    __syncthreads();
    if (t < 16) {
        float x = red[t];
        #pragma unroll
        for (int o = 8; o; o >>= 1) x = fmaxf(x, __shfl_xor_sync(0xffffu, x, o));
        if (t == 0) red[0] = x;
    }
    __syncthreads();
    m = red[0];
    __syncthreads();

    float sum = 0.f;
    #pragma unroll
    for (int i = 0; i < NL / 512; i++) {
        e[i] = expf(e[i] - m);
        sum += e[i];
    }
    float tot = block_sum_512(sum, red);
    float inv = 1.0f / tot;

    #pragma unroll
    for (int i = 0; i < NL / 512; i++) {
        int l = t + i * 512;
        float sv = e[i] * inv;
        g_s[b * NL + l] = sv;
        wout[((size_t)b * NL + l) * NBLK + blk] = sv;
    }
}

// partial A (R3-measured best) + one extra CTA column that warms W1/W2 into L2
// grid = dim3(NCHUNK + 1, NB), 128 threads
__global__ void apart_kernel(const float* __restrict__ v,
                             const float* __restrict__ W1,
                             const float* __restrict__ W2, int blk) {
    int c = blockIdx.x;     // 0..NCHUNK (last column = warm)
    int b = blockIdx.y;     // 0..31
    int t = threadIdx.x;    // 0..127

    if (c == NCHUNK) {
        // warm path: 32 CTAs x 128 thr touch W1[blk], W2[blk] (evict-normal).
        // Each array = ND*NDFF = 131072 floats = 32768 float4.
        // 4096 threads -> 8 float4 per thread per array.
        int idx = b * 128 + t;  // 0..4095
        const float4* w1 = reinterpret_cast<const float4*>(W1 + (size_t)blk * ND * NDFF);
        const float4* w2 = reinterpret_cast<const float4*>(W2 + (size_t)blk * ND * NDFF);
        float s = 0.f;
        #pragma unroll
        for (int i = 0; i < 8; i++) {
            float4 x1 = __ldg(w1 + idx + i * 4096);
            float4 x2 = __ldg(w2 + idx + i * 4096);
            s += x1.x + x1.w + x2.x + x2.w;
        }
        if (s == 123456789.0f) g_sink = s;   // never true; defeats DCE
        return;
    }

    __shared__ float ss[LCHUNK];
    if (t < LCHUNK) ss[t] = g_s[b * NL + c * LCHUNK + t];
    __syncthreads();
    const float4* vp = reinterpret_cast<const float4*>(
        v + ((size_t)b * NL + (size_t)c * LCHUNK) * ND) + t;  // row stride ND/4=128
    float4 a0 = {0,0,0,0}, a1 = {0,0,0,0}, a2 = {0,0,0,0}, a3 = {0,0,0,0};
    #pragma unroll 4
    for (int l = 0; l < LCHUNK; l += 4) {
        float4 v0 = __ldcs(vp + (l + 0) * 128);
        float4 v1 = __ldcs(vp + (l + 1) * 128);
        float4 v2 = __ldcs(vp + (l + 2) * 128);
        float4 v3 = __ldcs(vp + (l + 3) * 128);
        float s0 = ss[l + 0], s1 = ss[l + 1], s2 = ss[l + 2], s3 = ss[l + 3];
        a0.x = fmaf(s0, v0.x, a0.x); a0.y = fmaf(s0, v0.y, a0.y);
        a0.z = fmaf(s0, v0.z, a0.z); a0.w = fmaf(s0, v0.w, a0.w);
        a1.x = fmaf(s1, v1.x, a1.x); a1.y = fmaf(s1, v1.y, a1.y);
        a1.z = fmaf(s1, v1.z, a1.z); a1.w = fmaf(s1, v1.w, a1.w);
        a2.x = fmaf(s2, v2.x, a2.x); a2.y = fmaf(s2, v2.y, a2.y);
        a2.z = fmaf(s2, v2.z, a2.z); a2.w = fmaf(s2, v2.w, a2.w);
        a3.x = fmaf(s3, v3.x, a3.x); a3.y = fmaf(s3, v3.y, a3.y);
        a3.z = fmaf(s3, v3.z, a3.z); a3.w = fmaf(s3, v3.w, a3.w);
    }
    float4 r;
    r.x = (a0.x + a1.x) + (a2.x + a3.x);
    r.y = (a0.y + a1.y) + (a2.y + a3.y);
    r.z = (a0.z + a1.z) + (a2.z + a3.z);
    r.w = (a0.w + a1.w) + (a2.w + a3.w);
    reinterpret_cast<float4*>(g_Apart + (b * NCHUNK + c) * ND)[t] = r;
}

// fused tail: reduce partials + residual + Norm1 + FF(relu) + FF2 + residual + Norm2
__global__ void tail_kernel(const float* __restrict__ W1, const float* __restrict__ b1,
                            const float* __restrict__ W2, const float* __restrict__ b2,
                            const float* __restrict__ al1, const float* __restrict__ bi1,
                            const float* __restrict__ al2, const float* __restrict__ bi2,
                            float* __restrict__ out, int blk, int write_out, int out_off) {
    int b = blockIdx.x;   // 32
    int d = threadIdx.x;  // 512
    __shared__ float red[16];
    __shared__ float sh_q[ND];
    __shared__ float sh_p[ND];
    __shared__ float sh_h[NDFF];

    float x = g_q[b * ND + d];
    #pragma unroll 8
    for (int c = 0; c < NCHUNK; c++) x += g_Apart[(b * NCHUNK + c) * ND + d];

    float mu  = block_sum_512(x, red) * (1.0f / ND);
    float dev = x - mu;
    float var = block_sum_512(dev * dev, red) * (1.0f / (ND - 1));
    float qn1 = al1[blk * ND + d] * dev / (sqrtf(var) + FEPS) + bi1[blk * ND + d];
    sh_q[d] = qn1;
    __syncthreads();

    {
        int j    = d & (NDFF - 1);
        int half = d >> 8;
        const float* w  = W1 + (size_t)blk * ND * NDFF + (size_t)(half * 256) * NDFF + j;
        const float* xq = sh_q + half * 256;
        float c0 = 0.f, c1 = 0.f, c2 = 0.f, c3 = 0.f;
        float c4 = 0.f, c5 = 0.f, c6 = 0.f, c7 = 0.f;
        #pragma unroll 4
        for (int i = 0; i < 256; i += 8) {
            c0 = fmaf(xq[i + 0], __ldg(w + (i + 0) * NDFF), c0);
            c1 = fmaf(xq[i + 1], __ldg(w + (i + 1) * NDFF), c1);
            c2 = fmaf(xq[i + 2], __ldg(w + (i + 2) * NDFF), c2);
            c3 = fmaf(xq[i + 3], __ldg(w + (i + 3) * NDFF), c3);
            c4 = fmaf(xq[i + 4], __ldg(w + (i + 4) * NDFF), c4);
            c5 = fmaf(xq[i + 5], __ldg(w + (i + 5) * NDFF), c5);
            c6 = fmaf(xq[i + 6], __ldg(w + (i + 6) * NDFF), c6);
            c7 = fmaf(xq[i + 7], __ldg(w + (i + 7) * NDFF), c7);
        }
        sh_p[d] = ((c0 + c1) + (c2 + c3)) + ((c4 + c5) + (c6 + c7));
    }
    __syncthreads();
    if (d < NDFF) {
        float hv = sh_p[d] + sh_p[d + 256] + b1[blk * NDFF + d];
        sh_h[d] = fmaxf(hv, 0.f);
    }
    __syncthreads();

    float acc = b2[blk * ND + d];
    {
        const float* w2 = W2 + (size_t)blk * NDFF * ND + d;
        float c0 = 0.f, c1 = 0.f, c2 = 0.f, c3 = 0.f;
        float c4 = 0.f, c5 = 0.f, c6 = 0.f, c7 = 0.f;
        #pragma unroll 4
        for (int j = 0; j < NDFF; j += 8) {
            c0 = fmaf(sh_h[j + 0], __ldg(w2 + (j + 0) * ND), c0);
            c1 = fmaf(sh_h[j + 1], __ldg(w2 + (j + 1) * ND), c1);
            c2 = fmaf(sh_h[j + 2], __ldg(w2 + (j + 2) * ND), c2);
            c3 = fmaf(sh_h[j + 3], __ldg(w2 + (j + 3) * ND), c3);
            c4 = fmaf(sh_h[j + 4], __ldg(w2 + (j + 4) * ND), c4);
            c5 = fmaf(sh_h[j + 5], __ldg(w2 + (j + 5) * ND), c5);
            c6 = fmaf(sh_h[j + 6], __ldg(w2 + (j + 6) * ND), c6);
            c7 = fmaf(sh_h[j + 7], __ldg(w2 + (j + 7) * ND), c7);
        }
        acc += ((c0 + c1) + (c2 + c3)) + ((c4 + c5) + (c6 + c7));
    }
    float x2 = qn1 + acc;

    float mu2  = block_sum_512(x2, red) * (1.0f / ND);
    float dev2 = x2 - mu2;
    float var2 = block_sum_512(dev2 * dev2, red) * (1.0f / (ND - 1));
    float qn2 = al2[blk * ND + d] * dev2 / (sqrtf(var2) + FEPS) + bi2[blk * ND + d];

    g_q[b * ND + d] = qn2;
    if (write_out) out[b * (2 * ND) + out_off + d] = qn2;
}

// ---------------- launch ----------------
extern "C" void kernel_launch(void* const* d_in, const int* in_sizes, int n_in,
                              void* d_out, int out_size) {
    const float* q   = (const float*)d_in[0];
    const float* k   = (const float*)d_in[1];
    const float* v   = (const float*)d_in[2];
    const float* W1  = (const float*)d_in[3];
    const float* b1  = (const float*)d_in[4];
    const float* W2  = (const float*)d_in[5];
    const float* b2  = (const float*)d_in[6];
    const float* al1 = (const float*)d_in[7];
    const float* bi1 = (const float*)d_in[8];
    const float* al2 = (const float*)d_in[9];
    const float* bi2 = (const float*)d_in[10];

    float* out_p = (float*)d_out;                 // (32, 1024)
    float* w_p   = (float*)d_out + NB * 2 * ND;   // (32, 2048, 6)

    initq_kernel<<<(NB * ND + 255) / 256, 256>>>(q);

    for (int blk = 0; blk < NBLK; blk++) {
        scores_kernel<<<(NB * NL / 2 * 32) / 256, 256>>>(k);
        softmax_kernel<<<NB, 512>>>(w_p, blk);
        apart_kernel<<<dim3(NCHUNK + 1, NB), 128>>>(v, W1, W2, blk);
        int wr = (blk == 2 || blk == 5) ? 1 : 0;
        int off = (blk == 5) ? ND : 0;
        tail_kernel<<<NB, 512>>>(W1, b1, W2, b2, al1, bi1, al2, bi2,
                                 out_p, blk, wr, off);
    }
}

// round 12
// speedup vs baseline: 1.0168x; 1.0168x over previous
#include <cuda_runtime.h>
#include <math.h>

#define NB   32
#define NL   2048
#define ND   512
#define NDFF 256
#define NBLK 6
#define FEPS 1e-6f
#define LCHUNK 64
#define NCHUNK (NL / LCHUNK)   // 32

// ---------------- device scratch (no allocations allowed) ----------------
__device__ float g_q[NB * ND];              // evolving query
__device__ float g_scores[NB * NL];         // raw scores
__device__ float g_s[NB * NL];              // softmax probs (contiguous)
__device__ float g_Apart[NB * NCHUNK * ND]; // partial attention outputs
__device__ float g_sink;                    // DCE sink for warm loads

// ---------------- helpers ----------------
__device__ __forceinline__ float block_sum_512(float v, float* red) {
    #pragma unroll
    for (int o = 16; o; o >>= 1) v += __shfl_xor_sync(0xffffffffu, v, o);
    int w = threadIdx.x >> 5;
    if ((threadIdx.x & 31) == 0) red[w] = v;
    __syncthreads();
    if (threadIdx.x < 16) {
        float t = red[threadIdx.x];
        #pragma unroll
        for (int o = 8; o; o >>= 1) t += __shfl_xor_sync(0xffffu, t, o);
        if (threadIdx.x == 0) red[0] = t;
    }
    __syncthreads();
    float r = red[0];
    __syncthreads();
    return r;
}

__device__ __forceinline__ float dot4(float4 a, float4 b, float acc) {
    acc = fmaf(a.x, b.x, acc);
    acc = fmaf(a.y, b.y, acc);
    acc = fmaf(a.z, b.z, acc);
    acc = fmaf(a.w, b.w, acc);
    return acc;
}

// ---------------- kernels ----------------
__global__ void initq_kernel(const float* __restrict__ q) {
    int i = blockIdx.x * blockDim.x + threadIdx.x;
    if (i < NB * ND) g_q[i] = q[i];
}

// scores: TWO rows per warp; 8 x 16B loads in flight per lane
__global__ void scores_kernel(const float* __restrict__ k) {
    int warp = (blockIdx.x * blockDim.x + threadIdx.x) >> 5;  // 0..NB*NL/2-1
    int lane = threadIdx.x & 31;
    if (warp >= NB * NL / 2) return;
    int r0 = warp * 2;            // rows r0, r0+1 (same batch: 2048 rows per b)
    int b = r0 >> 11;
    const float4* kA = reinterpret_cast<const float4*>(k + (size_t)r0 * ND) + lane;
    const float4* kB = reinterpret_cast<const float4*>(k + (size_t)(r0 + 1) * ND) + lane;
    const float4* q4 = reinterpret_cast<const float4*>(g_q + b * ND) + lane;

    float4 a0 = __ldcs(kA + 0);
    float4 a1 = __ldcs(kA + 32);
    float4 a2 = __ldcs(kA + 64);
    float4 a3 = __ldcs(kA + 96);
    float4 b0 = __ldcs(kB + 0);
    float4 b1 = __ldcs(kB + 32);
    float4 b2 = __ldcs(kB + 64);
    float4 b3 = __ldcs(kB + 96);
    float4 q0 = q4[0], q1 = q4[32], q2 = q4[64], q3 = q4[96];

    float accA = 0.f, accB = 0.f;
    accA = dot4(a0, q0, accA); accB = dot4(b0, q0, accB);
    accA = dot4(a1, q1, accA); accB = dot4(b1, q1, accB);
    accA = dot4(a2, q2, accA); accB = dot4(b2, q2, accB);
    accA = dot4(a3, q3, accA); accB = dot4(b3, q3, accB);

    #pragma unroll
    for (int o = 16; o; o >>= 1) {
        accA += __shfl_xor_sync(0xffffffffu, accA, o);
        accB += __shfl_xor_sync(0xffffffffu, accB, o);
    }
    if (lane == 0) {
        const float s = 0.04419417382415922f;   // 1/sqrt(512)
        g_scores[r0]     = accA * s;
        g_scores[r0 + 1] = accB * s;
    }
}

// softmax over L per batch; writes contiguous g_s and strided weights[:, :, blk]
__global__ void softmax_kernel(float* __restrict__ wout, int blk) {
    int b = blockIdx.x;
    int t = threadIdx.x;            // 512 threads
    __shared__ float red[16];
    const float* sc = g_scores + b * NL;

    float e[NL / 512];
    float m = -INFINITY;
    #pragma unroll
    for (int i = 0; i < NL / 512; i++) {
        e[i] = sc[t + i * 512];
        m = fmaxf(m, e[i]);
    }
    #pragma unroll
    for (int o = 16; o; o >>= 1) m = fmaxf(m, __shfl_xor_sync(0xffffffffu, m, o));
    int w = t >> 5;
    if ((t & 31) == 0) red[w] = m;
    __syncthreads();
    if (t < 16) {
        float x = red[t];
        #pragma unroll
        for (int o = 8; o; o >>= 1) x = fmaxf(x, __shfl_xor_sync(0xffffu, x, o));
        if (t == 0) red[0] = x;
    }
    __syncthreads();
    m = red[0];
    __syncthreads();

    float sum = 0.f;
    #pragma unroll
    for (int i = 0; i < NL / 512; i++) {
        e[i] = expf(e[i] - m);
        sum += e[i];
    }
    float tot = block_sum_512(sum, red);
    float inv = 1.0f / tot;

    #pragma unroll
    for (int i = 0; i < NL / 512; i++) {
        int l = t + i * 512;
        float sv = e[i] * inv;
        g_s[b * NL + l] = sv;
        wout[((size_t)b * NL + l) * NBLK + blk] = sv;
    }
}

// partial A (R3 shape) + one extra CTA column that warms W1/W2 into L2
__global__ void apart_kernel(const float* __restrict__ v,
                             const float* __restrict__ W1,
                             const float* __restrict__ W2, int blk) {
    int c = blockIdx.x;     // 0..NCHUNK (last column = warm)
    int b = blockIdx.y;     // 0..31
    int t = threadIdx.x;    // 0..127

    if (c == NCHUNK) {
        int idx = b * 128 + t;  // 0..4095
        const float4* w1 = reinterpret_cast<const float4*>(W1 + (size_t)blk * ND * NDFF);
        const float4* w2 = reinterpret_cast<const float4*>(W2 + (size_t)blk * ND * NDFF);
        float s = 0.f;
        #pragma unroll
        for (int i = 0; i < 8; i++) {
            float4 x1 = __ldg(w1 + idx + i * 4096);
            float4 x2 = __ldg(w2 + idx + i * 4096);
            s += x1.x + x1.w + x2.x + x2.w;
        }
        if (s == 123456789.0f) g_sink = s;   // never true; defeats DCE
        return;
    }

    __shared__ float ss[LCHUNK];
    if (t < LCHUNK) ss[t] = g_s[b * NL + c * LCHUNK + t];
    __syncthreads();
    const float4* vp = reinterpret_cast<const float4*>(
        v + ((size_t)b * NL + (size_t)c * LCHUNK) * ND) + t;  // row stride ND/4=128
    float4 a0 = {0,0,0,0}, a1 = {0,0,0,0}, a2 = {0,0,0,0}, a3 = {0,0,0,0};
    #pragma unroll 4
    for (int l = 0; l < LCHUNK; l += 4) {
        float4 v0 = __ldcs(vp + (l + 0) * 128);
        float4 v1 = __ldcs(vp + (l + 1) * 128);
        float4 v2 = __ldcs(vp + (l + 2) * 128);
        float4 v3 = __ldcs(vp + (l + 3) * 128);
        float s0 = ss[l + 0], s1 = ss[l + 1], s2 = ss[l + 2], s3 = ss[l + 3];
        a0.x = fmaf(s0, v0.x, a0.x); a0.y = fmaf(s0, v0.y, a0.y);
        a0.z = fmaf(s0, v0.z, a0.z); a0.w = fmaf(s0, v0.w, a0.w);
        a1.x = fmaf(s1, v1.x, a1.x); a1.y = fmaf(s1, v1.y, a1.y);
        a1.z = fmaf(s1, v1.z, a1.z); a1.w = fmaf(s1, v1.w, a1.w);
        a2.x = fmaf(s2, v2.x, a2.x); a2.y = fmaf(s2, v2.y, a2.y);
        a2.z = fmaf(s2, v2.z, a2.z); a2.w = fmaf(s2, v2.w, a2.w);
        a3.x = fmaf(s3, v3.x, a3.x); a3.y = fmaf(s3, v3.y, a3.y);
        a3.z = fmaf(s3, v3.z, a3.z); a3.w = fmaf(s3, v3.w, a3.w);
    }
    float4 r;
    r.x = (a0.x + a1.x) + (a2.x + a3.x);
    r.y = (a0.y + a1.y) + (a2.y + a3.y);
    r.z = (a0.z + a1.z) + (a2.z + a3.z);
    r.w = (a0.w + a1.w) + (a2.w + a3.w);
    reinterpret_cast<float4*>(g_Apart + (b * NCHUNK + c) * ND)[t] = r;
}

// fused tail: reduce partials + residual + Norm1 + FF(relu) + FF2 + residual + Norm2
// FF loops use 16 loads in flight (halved latency waves vs R11)
__global__ void tail_kernel(const float* __restrict__ W1, const float* __restrict__ b1,
                            const float* __restrict__ W2, const float* __restrict__ b2,
                            const float* __restrict__ al1, const float* __restrict__ bi1,
                            const float* __restrict__ al2, const float* __restrict__ bi2,
                            float* __restrict__ out, int blk, int write_out, int out_off) {
    int b = blockIdx.x;   // 32
    int d = threadIdx.x;  // 512
    __shared__ float red[16];
    __shared__ float sh_q[ND];
    __shared__ float sh_p[ND];
    __shared__ float sh_h[NDFF];

    float x = g_q[b * ND + d];
    #pragma unroll 8
    for (int c = 0; c < NCHUNK; c++) x += g_Apart[(b * NCHUNK + c) * ND + d];

    float mu  = block_sum_512(x, red) * (1.0f / ND);
    float dev = x - mu;
    float var = block_sum_512(dev * dev, red) * (1.0f / (ND - 1));
    float qn1 = al1[blk * ND + d] * dev / (sqrtf(var) + FEPS) + bi1[blk * ND + d];
    sh_q[d] = qn1;
    __syncthreads();

    // FF1: 512 threads = (half, j); 16 loads in flight
    {
        int j    = d & (NDFF - 1);
        int half = d >> 8;
        const float* w  = W1 + (size_t)blk * ND * NDFF + (size_t)(half * 256) * NDFF + j;
        const float* xq = sh_q + half * 256;
        float c0 = 0.f, c1 = 0.f, c2 = 0.f, c3 = 0.f;
        float c4 = 0.f, c5 = 0.f, c6 = 0.f, c7 = 0.f;
        float c8 = 0.f, c9 = 0.f, cA = 0.f, cB = 0.f;
        float cC = 0.f, cD = 0.f, cE = 0.f, cF = 0.f;
        #pragma unroll
        for (int i = 0; i < 256; i += 16) {
            float w0 = __ldg(w + (i + 0) * NDFF);
            float w1v = __ldg(w + (i + 1) * NDFF);
            float w2v = __ldg(w + (i + 2) * NDFF);
            float w3 = __ldg(w + (i + 3) * NDFF);
            float w4 = __ldg(w + (i + 4) * NDFF);
            float w5 = __ldg(w + (i + 5) * NDFF);
            float w6 = __ldg(w + (i + 6) * NDFF);
            float w7 = __ldg(w + (i + 7) * NDFF);
            float w8 = __ldg(w + (i + 8) * NDFF);
            float w9 = __ldg(w + (i + 9) * NDFF);
            float wA = __ldg(w + (i + 10) * NDFF);
            float wB = __ldg(w + (i + 11) * NDFF);
            float wC = __ldg(w + (i + 12) * NDFF);
            float wD = __ldg(w + (i + 13) * NDFF);
            float wE = __ldg(w + (i + 14) * NDFF);
            float wF = __ldg(w + (i + 15) * NDFF);
            c0 = fmaf(xq[i + 0],  w0,  c0);
            c1 = fmaf(xq[i + 1],  w1v, c1);
            c2 = fmaf(xq[i + 2],  w2v, c2);
            c3 = fmaf(xq[i + 3],  w3,  c3);
            c4 = fmaf(xq[i + 4],  w4,  c4);
            c5 = fmaf(xq[i + 5],  w5,  c5);
            c6 = fmaf(xq[i + 6],  w6,  c6);
            c7 = fmaf(xq[i + 7],  w7,  c7);
            c8 = fmaf(xq[i + 8],  w8,  c8);
            c9 = fmaf(xq[i + 9],  w9,  c9);
            cA = fmaf(xq[i + 10], wA,  cA);
            cB = fmaf(xq[i + 11], wB,  cB);
            cC = fmaf(xq[i + 12], wC,  cC);
            cD = fmaf(xq[i + 13], wD,  cD);
            cE = fmaf(xq[i + 14], wE,  cE);
            cF = fmaf(xq[i + 15], wF,  cF);
        }
        sh_p[d] = (((c0 + c1) + (c2 + c3)) + ((c4 + c5) + (c6 + c7)))
                + (((c8 + c9) + (cA + cB)) + ((cC + cD) + (cE + cF)));
    }
    __syncthreads();
    if (d < NDFF) {
        float hv = sh_p[d] + sh_p[d + 256] + b1[blk * NDFF + d];
        sh_h[d] = fmaxf(hv, 0.f);
    }
    __syncthreads();

    // FF2: 512 threads, one output d each; 16 loads in flight
    float acc = b2[blk * ND + d];
    {
        const float* w2 = W2 + (size_t)blk * NDFF * ND + d;
        float c0 = 0.f, c1 = 0.f, c2 = 0.f, c3 = 0.f;
        float c4 = 0.f, c5 = 0.f, c6 = 0.f, c7 = 0.f;
        float c8 = 0.f, c9 = 0.f, cA = 0.f, cB = 0.f;
        float cC = 0.f, cD = 0.f, cE = 0.f, cF = 0.f;
        #pragma unroll
        for (int j = 0; j < NDFF; j += 16) {
            float w0 = __ldg(w2 + (j + 0) * ND);
            float w1v = __ldg(w2 + (j + 1) * ND);
            float w2v = __ldg(w2 + (j + 2) * ND);
            float w3 = __ldg(w2 + (j + 3) * ND);
            float w4 = __ldg(w2 + (j + 4) * ND);
            float w5 = __ldg(w2 + (j + 5) * ND);
            float w6 = __ldg(w2 + (j + 6) * ND);
            float w7 = __ldg(w2 + (j + 7) * ND);
            float w8 = __ldg(w2 + (j + 8) * ND);
            float w9 = __ldg(w2 + (j + 9) * ND);
            float wA = __ldg(w2 + (j + 10) * ND);
            float wB = __ldg(w2 + (j + 11) * ND);
            float wC = __ldg(w2 + (j + 12) * ND);
            float wD = __ldg(w2 + (j + 13) * ND);
            float wE = __ldg(w2 + (j + 14) * ND);
            float wF = __ldg(w2 + (j + 15) * ND);
            c0 = fmaf(sh_h[j + 0],  w0,  c0);
            c1 = fmaf(sh_h[j + 1],  w1v, c1);
            c2 = fmaf(sh_h[j + 2],  w2v, c2);
            c3 = fmaf(sh_h[j + 3],  w3,  c3);
            c4 = fmaf(sh_h[j + 4],  w4,  c4);
            c5 = fmaf(sh_h[j + 5],  w5,  c5);
            c6 = fmaf(sh_h[j + 6],  w6,  c6);
            c7 = fmaf(sh_h[j + 7],  w7,  c7);
            c8 = fmaf(sh_h[j + 8],  w8,  c8);
            c9 = fmaf(sh_h[j + 9],  w9,  c9);
            cA = fmaf(sh_h[j + 10], wA,  cA);
            cB = fmaf(sh_h[j + 11], wB,  cB);
            cC = fmaf(sh_h[j + 12], wC,  cC);
            cD = fmaf(sh_h[j + 13], wD,  cD);
            cE = fmaf(sh_h[j + 14], wE,  cE);
            cF = fmaf(sh_h[j + 15], wF,  cF);
        }
        acc += (((c0 + c1) + (c2 + c3)) + ((c4 + c5) + (c6 + c7)))
             + (((c8 + c9) + (cA + cB)) + ((cC + cD) + (cE + cF)));
    }
    float x2 = qn1 + acc;

    float mu2  = block_sum_512(x2, red) * (1.0f / ND);
    float dev2 = x2 - mu2;
    float var2 = block_sum_512(dev2 * dev2, red) * (1.0f / (ND - 1));
    float qn2 = al2[blk * ND + d] * dev2 / (sqrtf(var2) + FEPS) + bi2[blk * ND + d];

    g_q[b * ND + d] = qn2;
    if (write_out) out[b * (2 * ND) + out_off + d] = qn2;
}

// ---------------- launch ----------------
extern "C" void kernel_launch(void* const* d_in, const int* in_sizes, int n_in,
                              void* d_out, int out_size) {
    const float* q   = (const float*)d_in[0];
    const float* k   = (const float*)d_in[1];
    const float* v   = (const float*)d_in[2];
    const float* W1  = (const float*)d_in[3];
    const float* b1  = (const float*)d_in[4];
    const float* W2  = (const float*)d_in[5];
    const float* b2  = (const float*)d_in[6];
    const float* al1 = (const float*)d_in[7];
    const float* bi1 = (const float*)d_in[8];
    const float* al2 = (const float*)d_in[9];
    const float* bi2 = (const float*)d_in[10];

    float* out_p = (float*)d_out;                 // (32, 1024)
    float* w_p   = (float*)d_out + NB * 2 * ND;   // (32, 2048, 6)

    initq_kernel<<<(NB * ND + 255) / 256, 256>>>(q);

    for (int blk = 0; blk < NBLK; blk++) {
        scores_kernel<<<(NB * NL / 2 * 32) / 256, 256>>>(k);
        softmax_kernel<<<NB, 512>>>(w_p, blk);
        apart_kernel<<<dim3(NCHUNK + 1, NB), 128>>>(v, W1, W2, blk);
        int wr = (blk == 2 || blk == 5) ? 1 : 0;
        int off = (blk == 5) ? ND : 0;
        tail_kernel<<<NB, 512>>>(W1, b1, W2, b2, al1, bi1, al2, bi2,
                                 out_p, blk, wr, off);
    }
}

// round 15
// speedup vs baseline: 1.0320x; 1.0149x over previous
#include <cuda_runtime.h>
#include <math.h>

#define NB   32
#define NL   2048
#define ND   512
#define NDFF 256
#define NBLK 6
#define FEPS 1e-6f
#define LCHUNK 64
#define NCHUNK (NL / LCHUNK)   // 32

// ---------------- device scratch (no allocations allowed) ----------------
__device__ float g_q[NB * ND];              // evolving query
__device__ float g_scores[NB * NL];         // raw scores
__device__ float g_s_all[NBLK][NB * NL];    // softmax probs per block (contiguous)
__device__ float g_Apart[NB * NCHUNK * ND]; // partial attention outputs
__device__ float g_sink;                    // DCE sink for warm loads

// ---------------- helpers ----------------
__device__ __forceinline__ float block_sum_512(float v, float* red) {
    #pragma unroll
    for (int o = 16; o; o >>= 1) v += __shfl_xor_sync(0xffffffffu, v, o);
    int w = threadIdx.x >> 5;
    if ((threadIdx.x & 31) == 0) red[w] = v;
    __syncthreads();
    if (threadIdx.x < 16) {
        float t = red[threadIdx.x];
        #pragma unroll
        for (int o = 8; o; o >>= 1) t += __shfl_xor_sync(0xffffu, t, o);
        if (threadIdx.x == 0) red[0] = t;
    }
    __syncthreads();
    float r = red[0];
    __syncthreads();
    return r;
}

__device__ __forceinline__ float dot4(float4 a, float4 b, float acc) {
    acc = fmaf(a.x, b.x, acc);
    acc = fmaf(a.y, b.y, acc);
    acc = fmaf(a.z, b.z, acc);
    acc = fmaf(a.w, b.w, acc);
    return acc;
}

// ---------------- kernels ----------------
__global__ void initq_kernel(const float* __restrict__ q) {
    int i = blockIdx.x * blockDim.x + threadIdx.x;
    if (i < NB * ND) g_q[i] = q[i];
}

// scores: FOUR rows per warp; 16 x 16B loads in flight per lane
__global__ void scores_kernel(const float* __restrict__ k) {
    int warp = (blockIdx.x * blockDim.x + threadIdx.x) >> 5;  // 0..NB*NL/4-1
    int lane = threadIdx.x & 31;
    if (warp >= NB * NL / 4) return;
    int r0 = warp * 4;            // rows r0..r0+3 (2048 rows per b, aligned)
    int b = r0 >> 11;
    const float4* k0 = reinterpret_cast<const float4*>(k + (size_t)(r0 + 0) * ND) + lane;
    const float4* k1 = reinterpret_cast<const float4*>(k + (size_t)(r0 + 1) * ND) + lane;
    const float4* k2 = reinterpret_cast<const float4*>(k + (size_t)(r0 + 2) * ND) + lane;
    const float4* k3 = reinterpret_cast<const float4*>(k + (size_t)(r0 + 3) * ND) + lane;
    const float4* q4 = reinterpret_cast<const float4*>(g_q + b * ND) + lane;

    float4 a00 = __ldcs(k0 + 0);
    float4 a01 = __ldcs(k0 + 32);
    float4 a02 = __ldcs(k0 + 64);
    float4 a03 = __ldcs(k0 + 96);
    float4 a10 = __ldcs(k1 + 0);
    float4 a11 = __ldcs(k1 + 32);
    float4 a12 = __ldcs(k1 + 64);
    float4 a13 = __ldcs(k1 + 96);
    float4 a20 = __ldcs(k2 + 0);
    float4 a21 = __ldcs(k2 + 32);
    float4 a22 = __ldcs(k2 + 64);
    float4 a23 = __ldcs(k2 + 96);
    float4 a30 = __ldcs(k3 + 0);
    float4 a31 = __ldcs(k3 + 32);
    float4 a32 = __ldcs(k3 + 64);
    float4 a33 = __ldcs(k3 + 96);
    float4 q0 = q4[0], q1 = q4[32], q2 = q4[64], q3 = q4[96];

    float s0 = 0.f, s1 = 0.f, s2 = 0.f, s3 = 0.f;
    s0 = dot4(a00, q0, s0); s1 = dot4(a10, q0, s1);
    s2 = dot4(a20, q0, s2); s3 = dot4(a30, q0, s3);
    s0 = dot4(a01, q1, s0); s1 = dot4(a11, q1, s1);
    s2 = dot4(a21, q1, s2); s3 = dot4(a31, q1, s3);
    s0 = dot4(a02, q2, s0); s1 = dot4(a12, q2, s1);
    s2 = dot4(a22, q2, s2); s3 = dot4(a32, q2, s3);
    s0 = dot4(a03, q3, s0); s1 = dot4(a13, q3, s1);
    s2 = dot4(a23, q3, s2); s3 = dot4(a33, q3, s3);

    #pragma unroll
    for (int o = 16; o; o >>= 1) {
        s0 += __shfl_xor_sync(0xffffffffu, s0, o);
        s1 += __shfl_xor_sync(0xffffffffu, s1, o);
        s2 += __shfl_xor_sync(0xffffffffu, s2, o);
        s3 += __shfl_xor_sync(0xffffffffu, s3, o);
    }
    if (lane == 0) {
        const float sc = 0.04419417382415922f;   // 1/sqrt(512)
        g_scores[r0 + 0] = s0 * sc;
        g_scores[r0 + 1] = s1 * sc;
        g_scores[r0 + 2] = s2 * sc;
        g_scores[r0 + 3] = s3 * sc;
    }
}

// softmax over L per batch; writes contiguous g_s_all[blk] only
__global__ void softmax_kernel(int blk) {
    int b = blockIdx.x;
    int t = threadIdx.x;            // 512 threads
    __shared__ float red[16];
    const float* sc = g_scores + b * NL;

    float e[NL / 512];
    float m = -INFINITY;
    #pragma unroll
    for (int i = 0; i < NL / 512; i++) {
        e[i] = sc[t + i * 512];
        m = fmaxf(m, e[i]);
    }
    #pragma unroll
    for (int o = 16; o; o >>= 1) m = fmaxf(m, __shfl_xor_sync(0xffffffffu, m, o));
    int w = t >> 5;
    if ((t & 31) == 0) red[w] = m;
    __syncthreads();
    if (t < 16) {
        float x = red[t];
        #pragma unroll
        for (int o = 8; o; o >>= 1) x = fmaxf(x, __shfl_xor_sync(0xffffu, x, o));
        if (t == 0) red[0] = x;
    }
    __syncthreads();
    m = red[0];
    __syncthreads();

    float sum = 0.f;
    #pragma unroll
    for (int i = 0; i < NL / 512; i++) {
        e[i] = expf(e[i] - m);
        sum += e[i];
    }
    float tot = block_sum_512(sum, red);
    float inv = 1.0f / tot;

    #pragma unroll
    for (int i = 0; i < NL / 512; i++) {
        int l = t + i * 512;
        g_s_all[blk][b * NL + l] = e[i] * inv;
    }
}

// partial A (R3 shape) + one extra CTA column that warms W1/W2 into L2
__global__ void apart_kernel(const float* __restrict__ v,
                             const float* __restrict__ W1,
                             const float* __restrict__ W2, int blk) {
    int c = blockIdx.x;     // 0..NCHUNK (last column = warm)
    int b = blockIdx.y;     // 0..31
    int t = threadIdx.x;    // 0..127

    if (c == NCHUNK) {
        int idx = b * 128 + t;  // 0..4095
        const float4* w1 = reinterpret_cast<const float4*>(W1 + (size_t)blk * ND * NDFF);
        const float4* w2 = reinterpret_cast<const float4*>(W2 + (size_t)blk * ND * NDFF);
        float s = 0.f;
        #pragma unroll
        for (int i = 0; i < 8; i++) {
            float4 x1 = __ldg(w1 + idx + i * 4096);
            float4 x2 = __ldg(w2 + idx + i * 4096);
            s += x1.x + x1.w + x2.x + x2.w;
        }
        if (s == 123456789.0f) g_sink = s;   // never true; defeats DCE
        return;
    }

    __shared__ float ss[LCHUNK];
    if (t < LCHUNK) ss[t] = g_s_all[blk][b * NL + c * LCHUNK + t];
    __syncthreads();
    const float4* vp = reinterpret_cast<const float4*>(
        v + ((size_t)b * NL + (size_t)c * LCHUNK) * ND) + t;  // row stride ND/4=128
    float4 a0 = {0,0,0,0}, a1 = {0,0,0,0}, a2 = {0,0,0,0}, a3 = {0,0,0,0};
    #pragma unroll 4
    for (int l = 0; l < LCHUNK; l += 4) {
        float4 v0 = __ldcs(vp + (l + 0) * 128);
        float4 v1 = __ldcs(vp + (l + 1) * 128);
        float4 v2 = __ldcs(vp + (l + 2) * 128);
        float4 v3 = __ldcs(vp + (l + 3) * 128);
        float s0 = ss[l + 0], s1 = ss[l + 1], s2 = ss[l + 2], s3 = ss[l + 3];
        a0.x = fmaf(s0, v0.x, a0.x); a0.y = fmaf(s0, v0.y, a0.y);
        a0.z = fmaf(s0, v0.z, a0.z); a0.w = fmaf(s0, v0.w, a0.w);
        a1.x = fmaf(s1, v1.x, a1.x); a1.y = fmaf(s1, v1.y, a1.y);
        a1.z = fmaf(s1, v1.z, a1.z); a1.w = fmaf(s1, v1.w, a1.w);
        a2.x = fmaf(s2, v2.x, a2.x); a2.y = fmaf(s2, v2.y, a2.y);
        a2.z = fmaf(s2, v2.z, a2.z); a2.w = fmaf(s2, v2.w, a2.w);
        a3.x = fmaf(s3, v3.x, a3.x); a3.y = fmaf(s3, v3.y, a3.y);
        a3.z = fmaf(s3, v3.z, a3.z); a3.w = fmaf(s3, v3.w, a3.w);
    }
    float4 r;
    r.x = (a0.x + a1.x) + (a2.x + a3.x);
    r.y = (a0.y + a1.y) + (a2.y + a3.y);
    r.z = (a0.z + a1.z) + (a2.z + a3.z);
    r.w = (a0.w + a1.w) + (a2.w + a3.w);
    reinterpret_cast<float4*>(g_Apart + (b * NCHUNK + c) * ND)[t] = r;
}

// fused tail: reduce partials + residual + Norm1 + FF(relu) + FF2 + residual + Norm2
__global__ void tail_kernel(const float* __restrict__ W1, const float* __restrict__ b1,
                            const float* __restrict__ W2, const float* __restrict__ b2,
                            const float* __restrict__ al1, const float* __restrict__ bi1,
                            const float* __restrict__ al2, const float* __restrict__ bi2,
                            float* __restrict__ out, int blk, int write_out, int out_off) {
    int b = blockIdx.x;   // 32
    int d = threadIdx.x;  // 512
    __shared__ float red[16];
    __shared__ float sh_q[ND];
    __shared__ float sh_p[ND];
    __shared__ float sh_h[NDFF];

    float x = g_q[b * ND + d];
    #pragma unroll 8
    for (int c = 0; c < NCHUNK; c++) x += g_Apart[(b * NCHUNK + c) * ND + d];

    float mu  = block_sum_512(x, red) * (1.0f / ND);
    float dev = x - mu;
    float var = block_sum_512(dev * dev, red) * (1.0f / (ND - 1));
    float qn1 = al1[blk * ND + d] * dev / (sqrtf(var) + FEPS) + bi1[blk * ND + d];
    sh_q[d] = qn1;
    __syncthreads();

    // FF1: 512 threads = (half, j); 16 loads in flight
    {
        int j    = d & (NDFF - 1);
        int half = d >> 8;
        const float* w  = W1 + (size_t)blk * ND * NDFF + (size_t)(half * 256) * NDFF + j;
        const float* xq = sh_q + half * 256;
        float c0 = 0.f, c1 = 0.f, c2 = 0.f, c3 = 0.f;
        float c4 = 0.f, c5 = 0.f, c6 = 0.f, c7 = 0.f;
        float c8 = 0.f, c9 = 0.f, cA = 0.f, cB = 0.f;
        float cC = 0.f, cD = 0.f, cE = 0.f, cF = 0.f;
        #pragma unroll
        for (int i = 0; i < 256; i += 16) {
            float w0 = __ldg(w + (i + 0) * NDFF);
            float w1v = __ldg(w + (i + 1) * NDFF);
            float w2v = __ldg(w + (i + 2) * NDFF);
            float w3 = __ldg(w + (i + 3) * NDFF);
            float w4 = __ldg(w + (i + 4) * NDFF);
            float w5 = __ldg(w + (i + 5) * NDFF);
            float w6 = __ldg(w + (i + 6) * NDFF);
            float w7 = __ldg(w + (i + 7) * NDFF);
            float w8 = __ldg(w + (i + 8) * NDFF);
            float w9 = __ldg(w + (i + 9) * NDFF);
            float wA = __ldg(w + (i + 10) * NDFF);
            float wB = __ldg(w + (i + 11) * NDFF);
            float wC = __ldg(w + (i + 12) * NDFF);
            float wD = __ldg(w + (i + 13) * NDFF);
            float wE = __ldg(w + (i + 14) * NDFF);
            float wF = __ldg(w + (i + 15) * NDFF);
            c0 = fmaf(xq[i + 0],  w0,  c0);
            c1 = fmaf(xq[i + 1],  w1v, c1);
            c2 = fmaf(xq[i + 2],  w2v, c2);
            c3 = fmaf(xq[i + 3],  w3,  c3);
            c4 = fmaf(xq[i + 4],  w4,  c4);
            c5 = fmaf(xq[i + 5],  w5,  c5);
            c6 = fmaf(xq[i + 6],  w6,  c6);
            c7 = fmaf(xq[i + 7],  w7,  c7);
            c8 = fmaf(xq[i + 8],  w8,  c8);
            c9 = fmaf(xq[i + 9],  w9,  c9);
            cA = fmaf(xq[i + 10], wA,  cA);
            cB = fmaf(xq[i + 11], wB,  cB);
            cC = fmaf(xq[i + 12], wC,  cC);
            cD = fmaf(xq[i + 13], wD,  cD);
            cE = fmaf(xq[i + 14], wE,  cE);
            cF = fmaf(xq[i + 15], wF,  cF);
        }
        sh_p[d] = (((c0 + c1) + (c2 + c3)) + ((c4 + c5) + (c6 + c7)))
                + (((c8 + c9) + (cA + cB)) + ((cC + cD) + (cE + cF)));
    }
    __syncthreads();
    if (d < NDFF) {
        float hv = sh_p[d] + sh_p[d + 256] + b1[blk * NDFF + d];
        sh_h[d] = fmaxf(hv, 0.f);
    }
    __syncthreads();

    // FF2: 512 threads, one output d each; 16 loads in flight
    float acc = b2[blk * ND + d];
    {
        const float* w2 = W2 + (size_t)blk * NDFF * ND + d;
        float c0 = 0.f, c1 = 0.f, c2 = 0.f, c3 = 0.f;
        float c4 = 0.f, c5 = 0.f, c6 = 0.f, c7 = 0.f;
        float c8 = 0.f, c9 = 0.f, cA = 0.f, cB = 0.f;
        float cC = 0.f, cD = 0.f, cE = 0.f, cF = 0.f;
        #pragma unroll
        for (int j = 0; j < NDFF; j += 16) {
            float w0 = __ldg(w2 + (j + 0) * ND);
            float w1v = __ldg(w2 + (j + 1) * ND);
            float w2v = __ldg(w2 + (j + 2) * ND);
            float w3 = __ldg(w2 + (j + 3) * ND);
            float w4 = __ldg(w2 + (j + 4) * ND);
            float w5 = __ldg(w2 + (j + 5) * ND);
            float w6 = __ldg(w2 + (j + 6) * ND);
            float w7 = __ldg(w2 + (j + 7) * ND);
            float w8 = __ldg(w2 + (j + 8) * ND);
            float w9 = __ldg(w2 + (j + 9) * ND);
            float wA = __ldg(w2 + (j + 10) * ND);
            float wB = __ldg(w2 + (j + 11) * ND);
            float wC = __ldg(w2 + (j + 12) * ND);
            float wD = __ldg(w2 + (j + 13) * ND);
            float wE = __ldg(w2 + (j + 14) * ND);
            float wF = __ldg(w2 + (j + 15) * ND);
            c0 = fmaf(sh_h[j + 0],  w0,  c0);
            c1 = fmaf(sh_h[j + 1],  w1v, c1);
            c2 = fmaf(sh_h[j + 2],  w2v, c2);
            c3 = fmaf(sh_h[j + 3],  w3,  c3);
            c4 = fmaf(sh_h[j + 4],  w4,  c4);
            c5 = fmaf(sh_h[j + 5],  w5,  c5);
            c6 = fmaf(sh_h[j + 6],  w6,  c6);
            c7 = fmaf(sh_h[j + 7],  w7,  c7);
            c8 = fmaf(sh_h[j + 8],  w8,  c8);
            c9 = fmaf(sh_h[j + 9],  w9,  c9);
            cA = fmaf(sh_h[j + 10], wA,  cA);
            cB = fmaf(sh_h[j + 11], wB,  cB);
            cC = fmaf(sh_h[j + 12], wC,  cC);
            cD = fmaf(sh_h[j + 13], wD,  cD);
            cE = fmaf(sh_h[j + 14], wE,  cE);
            cF = fmaf(sh_h[j + 15], wF,  cF);
        }
        acc += (((c0 + c1) + (c2 + c3)) + ((c4 + c5) + (c6 + c7)))
             + (((c8 + c9) + (cA + cB)) + ((cC + cD) + (cE + cF)));
    }
    float x2 = qn1 + acc;

    float mu2  = block_sum_512(x2, red) * (1.0f / ND);
    float dev2 = x2 - mu2;
    float var2 = block_sum_512(dev2 * dev2, red) * (1.0f / (ND - 1));
    float qn2 = al2[blk * ND + d] * dev2 / (sqrtf(var2) + FEPS) + bi2[blk * ND + d];

    g_q[b * ND + d] = qn2;
    if (write_out) out[b * (2 * ND) + out_off + d] = qn2;
}

// final: assemble weights (B, L, NBLK) with contiguous 24B-per-row stores
__global__ void combine_kernel(float* __restrict__ wout) {
    int i = blockIdx.x * blockDim.x + threadIdx.x;  // (b*NL + l)
    if (i >= NB * NL) return;
    float vals[NBLK];
    #pragma unroll
    for (int blk = 0; blk < NBLK; blk++) vals[blk] = g_s_all[blk][i];
    float* o = wout + (size_t)i * NBLK;
    #pragma unroll
    for (int blk = 0; blk < NBLK; blk++) o[blk] = vals[blk];
}

// ---------------- launch ----------------
extern "C" void kernel_launch(void* const* d_in, const int* in_sizes, int n_in,
                              void* d_out, int out_size) {
    const float* q   = (const float*)d_in[0];
    const float* k   = (const float*)d_in[1];
    const float* v   = (const float*)d_in[2];
    const float* W1  = (const float*)d_in[3];
    const float* b1  = (const float*)d_in[4];
    const float* W2  = (const float*)d_in[5];
    const float* b2  = (const float*)d_in[6];
    const float* al1 = (const float*)d_in[7];
    const float* bi1 = (const float*)d_in[8];
    const float* al2 = (const float*)d_in[9];
    const float* bi2 = (const float*)d_in[10];

    float* out_p = (float*)d_out;                 // (32, 1024)
    float* w_p   = (float*)d_out + NB * 2 * ND;   // (32, 2048, 6)

    initq_kernel<<<(NB * ND + 255) / 256, 256>>>(q);

    for (int blk = 0; blk < NBLK; blk++) {
        scores_kernel<<<(NB * NL / 4 * 32) / 256, 256>>>(k);
        softmax_kernel<<<NB, 512>>>(blk);
        apart_kernel<<<dim3(NCHUNK + 1, NB), 128>>>(v, W1, W2, blk);
        int wr = (blk == 2 || blk == 5) ? 1 : 0;
        int off = (blk == 5) ? ND : 0;
        tail_kernel<<<NB, 512>>>(W1, b1, W2, b2, al1, bi1, al2, bi2,
                                 out_p, blk, wr, off);
    }
    combine_kernel<<<(NB * NL + 255) / 256, 256>>>(w_p);
}